// round 15
// baseline (speedup 1.0000x reference)
#include <cuda_runtime.h>
#include <cstdint>

#define NB   1024
#define NPG  64
#define EPG  1024
#define NEPG 256
#define NN   (NB*NPG)
#define NEDGE (NB*EPG)
#define EMB  64
#define HID  128
#define NCAT 100
#define NET  4
#define NOUT 101
#define OUTW (1 + NPG*NOUT + NEPG)   // 6721
#define STR  132                      // feature tile stride (floats)
#define AST  68                       // dense alpha stride (floats)

typedef unsigned long long ull;
typedef unsigned int u32;
typedef unsigned short u16;
typedef unsigned char u8;

// ---------------- device scratch ----------------
__device__ float g_P1[NCAT*HID];
__device__ float g_ea[2][NET];
__device__ u8    g_sedge[NEDGE];        // per-graph dst-sorted: src | attr<<6
__device__ u16   g_soff[NB*NPG];        // per-graph CSR start offsets
__device__ uint4 g_Bf[4][4096];         // fragment-order split-bf16 weights: c2_w, n_w1, e_w1, n_w2
__device__ float g_pool[NB*HID];        // per-graph pooled h2 (stop head)

// ---------------- helpers ----------------
__device__ __forceinline__ u32 bfpack(float lo, float hi) {
    u32 r; asm("cvt.rn.bf16x2.f32 %0, %1, %2;" : "=r"(r) : "f"(hi), "f"(lo)); return r;
}
__device__ __forceinline__ void split_pair(float x0, float x1, u32& ph, u32& pl) {
    ph = bfpack(x0, x1);
    float h0 = __uint_as_float(ph << 16);
    float h1 = __uint_as_float(ph & 0xFFFF0000u);
    pl = bfpack(x0 - h0, x1 - h1);
}
__device__ __forceinline__ void mma16816(float* c, const u32* a, u32 b0, u32 b1) {
    asm volatile(
        "mma.sync.aligned.m16n8k16.row.col.f32.bf16.bf16.f32 "
        "{%0,%1,%2,%3}, {%4,%5,%6,%7}, {%8,%9}, {%0,%1,%2,%3};"
        : "+f"(c[0]), "+f"(c[1]), "+f"(c[2]), "+f"(c[3])
        : "r"(a[0]), "r"(a[1]), "r"(a[2]), "r"(a[3]), "r"(b0), "r"(b1));
}

// 64x128 @ 128x{128|101} split-bf16; A f32 smem (stride STR), B fragments global.
// warp = (row half rh: 32 rows) x (col quarter ch4: 32 cols).
__device__ __forceinline__ void mma_block(const float* __restrict__ sA,
                                          const uint4* __restrict__ Bf,
                                          int wid, int lane, float acc[8][4]) {
    int ch4 = wid & 3, rh = wid >> 2;
    int rr = lane >> 2;
    int kc = (lane & 3) * 2;
    const float* pa = sA + (rh * 32 + rr) * STR;
    #pragma unroll
    for (int i = 0; i < 8; i++)
        #pragma unroll
        for (int j = 0; j < 4; j++) acc[i][j] = 0.f;
    #pragma unroll
    for (int ks = 0; ks < 8; ks++) {
        int k0 = ks * 16 + kc;
        u32 ah0[4], al0[4], ah1[4], al1[4];
        {
            float2 v00 = *(const float2*)(pa + k0);
            float2 v10 = *(const float2*)(pa + 8 * STR + k0);
            float2 v01 = *(const float2*)(pa + k0 + 8);
            float2 v11 = *(const float2*)(pa + 8 * STR + k0 + 8);
            split_pair(v00.x, v00.y, ah0[0], al0[0]);
            split_pair(v10.x, v10.y, ah0[1], al0[1]);
            split_pair(v01.x, v01.y, ah0[2], al0[2]);
            split_pair(v11.x, v11.y, ah0[3], al0[3]);
        }
        {
            const float* pb = pa + 16 * STR;
            float2 v00 = *(const float2*)(pb + k0);
            float2 v10 = *(const float2*)(pb + 8 * STR + k0);
            float2 v01 = *(const float2*)(pb + k0 + 8);
            float2 v11 = *(const float2*)(pb + 8 * STR + k0 + 8);
            split_pair(v00.x, v00.y, ah1[0], al1[0]);
            split_pair(v10.x, v10.y, ah1[1], al1[1]);
            split_pair(v01.x, v01.y, ah1[2], al1[2]);
            split_pair(v11.x, v11.y, ah1[3], al1[3]);
        }
        const uint4* bp = Bf + (ks << 9) + (ch4 << 7) + lane;
        #pragma unroll
        for (int nt = 0; nt < 4; nt++) {
            uint4 b = bp[nt << 5];
            mma16816(acc[nt],     ah0, b.x, b.y);
            mma16816(acc[nt],     al0, b.x, b.y);
            mma16816(acc[nt],     ah0, b.z, b.w);
            mma16816(acc[4 + nt], ah1, b.x, b.y);
            mma16816(acc[4 + nt], al1, b.x, b.y);
            mma16816(acc[4 + nt], ah1, b.z, b.w);
        }
    }
}

// ---------------- attention as dense-alpha MMA ----------------
// tIn: input features (f32, stride STR). Output written IN-PLACE to tIn.
// tFrag: scratch region for fragment-order split-bf16 features (32KB).
// alpha (64 x AST f32) aliases the start of tIn (input dead after frag build).
__device__ void attn_mma(float* __restrict__ tIn, float* __restrict__ tFrag,
                         const u8* __restrict__ sedge, const u16* __restrict__ soff,
                         const float* shas, const float* shad, const float* shb,
                         const float* shea, float* shs, float* shd,
                         float* pool, int doRelu, int tid)
{
    int lane = tid & 31, w = tid >> 5;
    uint4* hf = (uint4*)tFrag;
    float* alpha = tIn;

    // --- phase 1: per-node scalars s,d  +  feature fragment build (both read tIn) ---
    for (int r = w; r < NPG; r += 8) {
        float ss = 0.f, dd = 0.f;
        #pragma unroll
        for (int u = 0; u < 4; u++) {
            int c = lane + 32 * u;
            float hv = tIn[r * STR + c];
            ss += hv * shas[c]; dd += hv * shad[c];
        }
        #pragma unroll
        for (int o = 16; o; o >>= 1) {
            ss += __shfl_down_sync(0xffffffffu, ss, o);
            dd += __shfl_down_sync(0xffffffffu, dd, o);
        }
        if (lane == 0) { shs[r] = ss; shd[r] = dd; }
    }
    // hfrag: [ks(4)][nt(16)][lane(32)] uint4 {bh0,bh1,bl0,bl1}; k=src row, n=feature col
    for (int i = tid; i < 2048; i += 256) {
        int ks = i >> 9, rest = i & 511;
        int nt = rest >> 5, l = rest & 31;
        int k = ks * 16 + (l & 3) * 2;
        int n = nt * 8 + (l >> 2);
        u32 bh0, bl0, bh1, bl1;
        split_pair(tIn[k * STR + n],       tIn[(k + 1) * STR + n], bh0, bl0);
        split_pair(tIn[(k + 8) * STR + n], tIn[(k + 9) * STR + n], bh1, bl1);
        hf[i] = make_uint4(bh0, bh1, bl0, bl1);
    }
    __syncthreads();

    // --- phase 2: zero alpha (overwrites dead input region) ---
    for (int i = tid; i < NPG * AST; i += 256) alpha[i] = 0.f;
    __syncthreads();

    // --- phase 3: scatter exp(logit) into alpha; inv-den -> shd ---
    // two dsts per warp (half-warp each)
    {
        int hl = lane & 15;
        int hsel = lane >> 4;
        #pragma unroll
        for (int i = 0; i < 4; i++) {
            int dl = w + 8 * hsel + 16 * i;
            int st = soff[dl];
            int en = (dl < NPG - 1) ? soff[dl + 1] : EPG;
            float db = shd[dl];
            float den = 0.f;
            for (int j = st + hl; j < en; j += 16) {
                u32 p = sedge[j];
                int sl = p & 63;
                float lg = shs[sl] + db + shea[p >> 6];
                lg = lg > 0.f ? lg : 0.2f * lg;
                float ex = __expf(lg);
                atomicAdd(&alpha[dl * AST + sl], ex);
                den += ex;
            }
            #pragma unroll
            for (int o = 8; o; o >>= 1) den += __shfl_xor_sync(0xffffffffu, den, o);
            if (hl == 0) shd[dl] = 1.f / (den + 1e-16f);
        }
    }
    __syncthreads();

    // --- phase 4: out = alpha @ hfrag (split-bf16, K=64) ---
    int ch4 = w & 3, rh = w >> 2;
    int rr = lane >> 2, kc = (lane & 3) * 2;
    float acc[8][4];
    #pragma unroll
    for (int i = 0; i < 8; i++)
        #pragma unroll
        for (int j = 0; j < 4; j++) acc[i][j] = 0.f;
    const float* pa = alpha + (rh * 32 + rr) * AST;
    #pragma unroll
    for (int ks = 0; ks < 4; ks++) {
        int k0 = ks * 16 + kc;
        u32 ah0[4], al0[4], ah1[4], al1[4];
        {
            float2 v00 = *(const float2*)(pa + k0);
            float2 v10 = *(const float2*)(pa + 8 * AST + k0);
            float2 v01 = *(const float2*)(pa + k0 + 8);
            float2 v11 = *(const float2*)(pa + 8 * AST + k0 + 8);
            split_pair(v00.x, v00.y, ah0[0], al0[0]);
            split_pair(v10.x, v10.y, ah0[1], al0[1]);
            split_pair(v01.x, v01.y, ah0[2], al0[2]);
            split_pair(v11.x, v11.y, ah0[3], al0[3]);
        }
        {
            const float* pb = pa + 16 * AST;
            float2 v00 = *(const float2*)(pb + k0);
            float2 v10 = *(const float2*)(pb + 8 * AST + k0);
            float2 v01 = *(const float2*)(pb + k0 + 8);
            float2 v11 = *(const float2*)(pb + 8 * AST + k0 + 8);
            split_pair(v00.x, v00.y, ah1[0], al1[0]);
            split_pair(v10.x, v10.y, ah1[1], al1[1]);
            split_pair(v01.x, v01.y, ah1[2], al1[2]);
            split_pair(v11.x, v11.y, ah1[3], al1[3]);
        }
        const uint4* bp = hf + (ks << 9) + (ch4 << 7) + lane;
        #pragma unroll
        for (int nt = 0; nt < 4; nt++) {
            uint4 b = bp[nt << 5];
            mma16816(acc[nt],     ah0, b.x, b.y);
            mma16816(acc[nt],     al0, b.x, b.y);
            mma16816(acc[nt],     ah0, b.z, b.w);
            mma16816(acc[4 + nt], ah1, b.x, b.y);
            mma16816(acc[4 + nt], al1, b.x, b.y);
            mma16816(acc[4 + nt], ah1, b.z, b.w);
        }
    }
    __syncthreads();   // all alpha reads complete before output overwrites it

    // --- phase 5: epilogue: scale by inv-den, bias, relu, write back to tIn; pool ---
    #pragma unroll
    for (int nt = 0; nt < 4; nt++) {
        int c = ch4 * 32 + nt * 8 + kc;
        float bb0 = shb[c], bb1 = shb[c + 1];
        float ps0 = 0.f, ps1 = 0.f;
        #pragma unroll
        for (int rt = 0; rt < 2; rt++) {
            int r0 = rh * 32 + rt * 16 + rr;
            float inv0 = shd[r0], inv8 = shd[r0 + 8];
            float* a = acc[rt * 4 + nt];
            float v0 = fmaf(a[0], inv0, bb0);
            float v1 = fmaf(a[1], inv0, bb1);
            float v2 = fmaf(a[2], inv8, bb0);
            float v3 = fmaf(a[3], inv8, bb1);
            if (doRelu) { v0 = fmaxf(v0,0.f); v1 = fmaxf(v1,0.f); v2 = fmaxf(v2,0.f); v3 = fmaxf(v3,0.f); }
            *(float2*)&tIn[r0 * STR + c]       = make_float2(v0, v1);
            *(float2*)&tIn[(r0 + 8) * STR + c] = make_float2(v2, v3);
            ps0 += v0 + v2; ps1 += v1 + v3;
        }
        if (pool) {
            atomicAdd(&pool[c],     ps0);
            atomicAdd(&pool[c + 1], ps1);
        }
    }
}

// ---------------- prep kernels ----------------
__global__ void prep_main(const float* __restrict__ node_tab,
                          const float* __restrict__ edge_tab,
                          const float* __restrict__ c1_w,
                          const float* __restrict__ c1_we,
                          const float* __restrict__ c1_ae,
                          const float* __restrict__ c2_we,
                          const float* __restrict__ c2_ae) {
    __shared__ float red[HID];
    int bid = blockIdx.x, tid = threadIdx.x;
    if (bid < NCAT) {
        float acc = 0.f;
        #pragma unroll 8
        for (int k = 0; k < EMB; k++) acc += node_tab[bid*EMB + k] * c1_w[k*HID + tid];
        g_P1[bid*HID + tid] = acc;
    } else {
        for (int combo = 0; combo < 2*NET; combo++) {
            int layer = combo >> 2, t = combo & 3;
            const float* We = layer ? c2_we : c1_we;
            const float* ae = layer ? c2_ae : c1_ae;
            float acc = 0.f;
            #pragma unroll 8
            for (int k = 0; k < EMB; k++) acc += edge_tab[t*EMB + k] * We[k*HID + tid];
            red[tid] = acc * ae[tid];
            __syncthreads();
            if (tid < 32) {
                float s = red[tid] + red[tid+32] + red[tid+64] + red[tid+96];
                #pragma unroll
                for (int o = 16; o; o >>= 1) s += __shfl_down_sync(0xffffffffu, s, o);
                if (tid == 0) g_ea[layer][t] = s;
            }
            __syncthreads();
        }
    }
}

__global__ void prep_w(const float* __restrict__ w0, const float* __restrict__ w1,
                       const float* __restrict__ w2, const float* __restrict__ w3) {
    int b = blockIdx.x, tid = threadIdx.x;
    const float* W = (b == 0) ? w0 : (b == 1) ? w1 : (b == 2) ? w2 : w3;
    int CW = (b == 3) ? NOUT : HID;
    for (int i = tid; i < 4096; i += 256) {
        int ks = i >> 9, rest = i & 511;
        int nt = rest >> 5, l = rest & 31;
        int k = ks * 16 + (l & 3) * 2;
        int n = nt * 8 + (l >> 2);
        float w00=0.f, w01=0.f, w10=0.f, w11=0.f;
        if (n < CW) {
            w00 = W[(size_t)k * CW + n];
            w01 = W[(size_t)(k+1) * CW + n];
            w10 = W[(size_t)(k+8) * CW + n];
            w11 = W[(size_t)(k+9) * CW + n];
        }
        u32 bh0, bl0, bh1, bl1;
        split_pair(w00, w01, bh0, bl0);
        split_pair(w10, w11, bh1, bl1);
        g_Bf[b][i] = make_uint4(bh0, bh1, bl0, bl1);
    }
}

__global__ __launch_bounds__(256) void prep_csr(const int* __restrict__ ei,
                                                const int* __restrict__ eat) {
    __shared__ int cnt[NPG], woff[NPG];
    int g = blockIdx.x, tid = threadIdx.x;
    int ebase = g * EPG;
    if (tid < NPG) cnt[tid] = 0;
    __syncthreads();
    for (int e = tid; e < EPG; e += 256)
        atomicAdd(&cnt[ei[NEDGE + ebase + e] & 63], 1);
    __syncthreads();
    if (tid == 0) {
        int run = 0;
        for (int i = 0; i < NPG; i++) {
            woff[i] = run;
            g_soff[g * NPG + i] = (u16)run;
            run += cnt[i];
        }
    }
    __syncthreads();
    for (int e = tid; e < EPG; e += 256) {
        int sl = ei[ebase + e] & 63;
        int dl = ei[NEDGE + ebase + e] & 63;
        int at = eat[ebase + e];
        int pos = atomicAdd(&woff[dl], 1);
        g_sedge[ebase + pos] = (u8)(sl | (at << 6));
    }
}

// ---------------- mega kernel ----------------
struct MS {
    float tA[NPG*STR];     // P1 -> h1 -> (frag L2) -> t -> q
    float tB[NPG*STR];     // (frag L1) -> hw -> h2
    u8    sedge[EPG];
    u16   soff[NPG];
    float shs[NPG], shd[NPG];
    float shas[HID], shad[HID], shb[HID];
    float sheb1[HID], shew2[HID];
    float pool[HID];
    float shea[NET];
    int   codes[NPG];
};

__global__ __launch_bounds__(256, 3) void mega(
    const int* __restrict__ x,
    const float* __restrict__ c1_as, const float* __restrict__ c1_ad, const float* __restrict__ c1_b,
    const float* __restrict__ c2_as, const float* __restrict__ c2_ad, const float* __restrict__ c2_b,
    const float* __restrict__ n_b1, const float* __restrict__ n_b2,
    const float* __restrict__ e_b1, const float* __restrict__ e_w2, const float* __restrict__ e_b2,
    const int* __restrict__ non_edges,
    float* __restrict__ out)
{
    extern __shared__ char smraw[];
    MS& S = *(MS*)smraw;
    int g = blockIdx.x, tid = threadIdx.x;
    int lane = tid & 31, wid = tid >> 5;

    // ---- load structure + layer1 params ----
    if (tid < HID) {
        S.shas[tid] = c1_as[tid]; S.shad[tid] = c1_ad[tid]; S.shb[tid] = c1_b[tid];
        S.sheb1[tid] = e_b1[tid]; S.shew2[tid] = e_w2[tid];
        S.pool[tid] = 0.f;
    }
    if (tid < NET) S.shea[tid] = g_ea[0][tid];
    if (tid < NPG) {
        S.codes[tid] = x[g * NPG + tid];
        S.soff[tid] = g_soff[g * NPG + tid];
    }
    for (int i = tid; i < EPG; i += 256) S.sedge[i] = g_sedge[g * EPG + i];
    __syncthreads();
    // P1 lookup -> tA
    for (int i = tid; i < NPG * 32; i += 256) {
        int r = i >> 5, qq = i & 31;
        *(float4*)&S.tA[r * STR + qq * 4] = ((const float4*)(g_P1 + S.codes[r] * HID))[qq];
    }
    __syncthreads();

    // ---- GAT layer 1: in-place tA -> h1(tA); frag scratch in tB ----
    attn_mma(S.tA, S.tB, S.sedge, S.soff, S.shas, S.shad, S.shb, S.shea,
             S.shs, S.shd, nullptr, 1, tid);
    __syncthreads();

    int ch4 = wid & 3, rh = wid >> 2;
    int rr = lane >> 2, kc = (lane & 3) * 2;
    float acc[8][4];

    // ---- hw = h1(tA) @ c2_w -> tB ; swap layer2 params ----
    mma_block(S.tA, g_Bf[0], wid, lane, acc);
    __syncthreads();
    #pragma unroll
    for (int rt = 0; rt < 2; rt++)
        #pragma unroll
        for (int nt = 0; nt < 4; nt++) {
            int r0 = rh * 32 + rt * 16 + rr;
            int c = ch4 * 32 + nt * 8 + kc;
            float* a = acc[rt * 4 + nt];
            *(float2*)&S.tB[r0 * STR + c] = make_float2(a[0], a[1]);
            *(float2*)&S.tB[(r0 + 8) * STR + c] = make_float2(a[2], a[3]);
        }
    if (tid < HID) { S.shas[tid] = c2_as[tid]; S.shad[tid] = c2_ad[tid]; S.shb[tid] = c2_b[tid]; }
    if (tid < NET) S.shea[tid] = g_ea[1][tid];
    __syncthreads();

    // ---- GAT layer 2: in-place tB -> h2(tB); frag scratch in tA ; pool ----
    attn_mma(S.tB, S.tA, S.sedge, S.soff, S.shas, S.shad, S.shb, S.shea,
             S.shs, S.shd, S.pool, 0, tid);
    __syncthreads();

    // ---- pool -> global for stop head kernel ----
    if (tid < HID) g_pool[g * HID + tid] = S.pool[tid];

    // ---- t = relu(h2(tB) @ n_w1 + n_b1) -> tA ----
    mma_block(S.tB, g_Bf[1], wid, lane, acc);
    __syncthreads();
    #pragma unroll
    for (int rt = 0; rt < 2; rt++)
        #pragma unroll
        for (int nt = 0; nt < 4; nt++) {
            int r0 = rh * 32 + rt * 16 + rr;
            int c = ch4 * 32 + nt * 8 + kc;
            float* a = acc[rt * 4 + nt];
            float b0 = n_b1[c], b1v = n_b1[c + 1];
            *(float2*)&S.tA[r0 * STR + c] =
                make_float2(fmaxf(a[0] + b0, 0.f), fmaxf(a[1] + b1v, 0.f));
            *(float2*)&S.tA[(r0 + 8) * STR + c] =
                make_float2(fmaxf(a[2] + b0, 0.f), fmaxf(a[3] + b1v, 0.f));
        }
    __syncthreads();

    // ---- addnode = t(tA) @ n_w2 + n_b2 -> out ----
    mma_block(S.tA, g_Bf[3], wid, lane, acc);
    size_t gbase = (size_t)g * OUTW + 1;
    #pragma unroll
    for (int rt = 0; rt < 2; rt++)
        #pragma unroll
        for (int nt = 0; nt < 4; nt++) {
            int r0 = rh * 32 + rt * 16 + rr;
            int c = ch4 * 32 + nt * 8 + kc;
            float* a = acc[rt * 4 + nt];
            size_t b0p = gbase + (size_t)r0 * NOUT;
            size_t b8p = gbase + (size_t)(r0 + 8) * NOUT;
            if (c < NOUT)     { float bb = n_b2[c];   out[b0p + c]   = a[0] + bb; out[b8p + c]   = a[2] + bb; }
            if (c + 1 < NOUT) { float bb = n_b2[c+1]; out[b0p + c+1] = a[1] + bb; out[b8p + c+1] = a[3] + bb; }
        }
    __syncthreads();

    // ---- q = h2(tB) @ e_w1 -> tA ----
    mma_block(S.tB, g_Bf[2], wid, lane, acc);
    #pragma unroll
    for (int rt = 0; rt < 2; rt++)
        #pragma unroll
        for (int nt = 0; nt < 4; nt++) {
            int r0 = rh * 32 + rt * 16 + rr;
            int c = ch4 * 32 + nt * 8 + kc;
            float* a = acc[rt * 4 + nt];
            *(float2*)&S.tA[r0 * STR + c] = make_float2(a[0], a[1]);
            *(float2*)&S.tA[(r0 + 8) * STR + c] = make_float2(a[2], a[3]);
        }
    __syncthreads();

    // ---- addedge head (q in tA) ----
    int nebase = g * NEPG;
    float eb2 = e_b2[0];
    for (int ne = wid; ne < NEPG; ne += 8) {
        int u = non_edges[(size_t)(nebase + ne) * 2]     & 63;
        int v = non_edges[(size_t)(nebase + ne) * 2 + 1] & 63;
        float acc2 = 0.f;
        #pragma unroll
        for (int uu = 0; uu < 4; uu++) {
            int c = lane + 32 * uu;
            float tv = S.tA[u * STR + c] + S.tA[v * STR + c] + S.sheb1[c];
            tv = fmaxf(tv, 0.f);
            acc2 += tv * S.shew2[c];
        }
        #pragma unroll
        for (int o = 16; o; o >>= 1) acc2 += __shfl_down_sync(0xffffffffu, acc2, o);
        if (lane == 0) out[(size_t)g * OUTW + 1 + NPG * NOUT + ne] = acc2 + eb2;
    }
}

// ---------------- stop head kernel: 2 graphs per block ----------------
__global__ __launch_bounds__(256) void stop_kernel(
    const float* __restrict__ s_w1, const float* __restrict__ s_b1,
    const float* __restrict__ s_w2, const float* __restrict__ s_b2,
    float* __restrict__ out)
{
    __shared__ float shp[2][HID];
    __shared__ float shz[2][HID];
    int tid = threadIdx.x;
    int half = tid >> 7, ht = tid & 127;
    int g = blockIdx.x * 2 + half;
    shp[half][ht] = g_pool[g * HID + ht];
    __syncthreads();
    float acc = s_b1[ht];
    #pragma unroll 8
    for (int k = 0; k < HID; k++) acc += shp[half][k] * s_w1[k * HID + ht];
    shz[half][ht] = fmaxf(acc, 0.f) * s_w2[ht];
    __syncthreads();
    int lane = tid & 31, w4 = ht >> 5;
    if (w4 == 0) {
        float s_ = shz[half][lane] + shz[half][lane + 32] + shz[half][lane + 64] + shz[half][lane + 96];
        #pragma unroll
        for (int o = 16; o; o >>= 1) s_ += __shfl_down_sync(0xffffffffu, s_, o);
        if (lane == 0) out[(size_t)g * OUTW] = s_ + s_b2[0];
    }
}

// ---------------- launch ----------------
extern "C" void kernel_launch(void* const* d_in, const int* in_sizes, int n_in,
                              void* d_out, int out_size) {
    const float* node_tab = (const float*)d_in[0];
    const float* edge_tab = (const float*)d_in[1];
    const float* c1_w  = (const float*)d_in[2];
    const float* c1_we = (const float*)d_in[3];
    const float* c1_as = (const float*)d_in[4];
    const float* c1_ad = (const float*)d_in[5];
    const float* c1_ae = (const float*)d_in[6];
    const float* c1_b  = (const float*)d_in[7];
    const float* c2_w  = (const float*)d_in[8];
    const float* c2_we = (const float*)d_in[9];
    const float* c2_as = (const float*)d_in[10];
    const float* c2_ad = (const float*)d_in[11];
    const float* c2_ae = (const float*)d_in[12];
    const float* c2_b  = (const float*)d_in[13];
    const float* s_w1  = (const float*)d_in[14];
    const float* s_b1  = (const float*)d_in[15];
    const float* s_w2  = (const float*)d_in[16];
    const float* s_b2  = (const float*)d_in[17];
    const float* n_w1  = (const float*)d_in[18];
    const float* n_b1  = (const float*)d_in[19];
    const float* n_w2  = (const float*)d_in[20];
    const float* n_b2  = (const float*)d_in[21];
    const float* e_w1  = (const float*)d_in[22];
    const float* e_b1  = (const float*)d_in[23];
    const float* e_w2  = (const float*)d_in[24];
    const float* e_b2  = (const float*)d_in[25];
    const int* x          = (const int*)d_in[26];
    const int* edge_index = (const int*)d_in[27];
    const int* edge_attr  = (const int*)d_in[28];
    const int* non_edges  = (const int*)d_in[29];
    float* out = (float*)d_out;

    cudaFuncSetAttribute(mega, cudaFuncAttributeMaxDynamicSharedMemorySize, (int)sizeof(MS));

    prep_main<<<NCAT + 1, HID>>>(node_tab, edge_tab, c1_w, c1_we, c1_ae, c2_we, c2_ae);
    prep_w<<<4, 256>>>(c2_w, n_w1, e_w1, n_w2);
    prep_csr<<<NB, 256>>>(edge_index, edge_attr);
    mega<<<NB, 256, sizeof(MS)>>>(x, c1_as, c1_ad, c1_b, c2_as, c2_ad, c2_b,
                                  n_b1, n_b2, e_b1, e_w2, e_b2, non_edges, out);
    stop_kernel<<<NB/2, 256>>>(s_w1, s_b1, s_w2, s_b2, out);
}

// round 17
// speedup vs baseline: 1.0387x; 1.0387x over previous
#include <cuda_runtime.h>
#include <cstdint>

#define NB   1024
#define NPG  64
#define EPG  1024
#define NEPG 256
#define NN   (NB*NPG)
#define NEDGE (NB*EPG)
#define EMB  64
#define HID  128
#define NCAT 100
#define NET  4
#define NOUT 101
#define OUTW (1 + NPG*NOUT + NEPG)   // 6721
#define STR  132                      // feature tile stride (floats)

typedef unsigned long long ull;
typedef unsigned int u32;
typedef unsigned short u16;
typedef unsigned char u8;

// ---------------- device scratch ----------------
__device__ float g_P1[NCAT*HID];
__device__ float g_ea[2][NET];
__device__ u8    g_sedge[NEDGE];        // per-graph dst-sorted: src | attr<<6
__device__ u16   g_soff[NB*NPG];        // per-graph CSR start offsets
__device__ uint4 g_Bf[4][4096];         // fragment-order split-bf16 weights: c2_w, n_w1, e_w1, n_w2
__device__ float g_pool[NB*HID];        // per-graph pooled h2 (stop head)

// ---------------- helpers ----------------
__device__ __forceinline__ ull pk2(float lo, float hi) {
    ull r; asm("mov.b64 %0, {%1,%2};" : "=l"(r) : "f"(lo), "f"(hi)); return r;
}
__device__ __forceinline__ void fma2(ull& d, ull a, ull b) {
    asm("fma.rn.f32x2 %0, %1, %2, %0;" : "+l"(d) : "l"(a), "l"(b));
}
__device__ __forceinline__ void upk2(ull v, float& lo, float& hi) {
    asm("mov.b64 {%0,%1}, %2;" : "=f"(lo), "=f"(hi) : "l"(v));
}
__device__ __forceinline__ u32 bfpack(float lo, float hi) {
    u32 r; asm("cvt.rn.bf16x2.f32 %0, %1, %2;" : "=r"(r) : "f"(hi), "f"(lo)); return r;
}
__device__ __forceinline__ void split_pair(float x0, float x1, u32& ph, u32& pl) {
    ph = bfpack(x0, x1);
    float h0 = __uint_as_float(ph << 16);
    float h1 = __uint_as_float(ph & 0xFFFF0000u);
    pl = bfpack(x0 - h0, x1 - h1);
}
__device__ __forceinline__ void mma16816(float* c, const u32* a, u32 b0, u32 b1) {
    asm volatile(
        "mma.sync.aligned.m16n8k16.row.col.f32.bf16.bf16.f32 "
        "{%0,%1,%2,%3}, {%4,%5,%6,%7}, {%8,%9}, {%0,%1,%2,%3};"
        : "+f"(c[0]), "+f"(c[1]), "+f"(c[2]), "+f"(c[3])
        : "r"(a[0]), "r"(a[1]), "r"(a[2]), "r"(a[3]), "r"(b0), "r"(b1));
}

// 64x128 @ 128x128 split-bf16; A f32 smem (stride STR), B fragments global.
// warp = (row half rh: 32 rows) x (col quarter ch4: 32 cols).
__device__ __forceinline__ void mma_block(const float* __restrict__ sA,
                                          const uint4* __restrict__ Bf,
                                          int wid, int lane, float acc[8][4]) {
    int ch4 = wid & 3, rh = wid >> 2;
    int rr = lane >> 2;
    int kc = (lane & 3) * 2;
    const float* pa = sA + (rh * 32 + rr) * STR;
    #pragma unroll
    for (int i = 0; i < 8; i++)
        #pragma unroll
        for (int j = 0; j < 4; j++) acc[i][j] = 0.f;
    #pragma unroll
    for (int ks = 0; ks < 8; ks++) {
        int k0 = ks * 16 + kc;
        u32 ah0[4], al0[4], ah1[4], al1[4];
        {
            float2 v00 = *(const float2*)(pa + k0);
            float2 v10 = *(const float2*)(pa + 8 * STR + k0);
            float2 v01 = *(const float2*)(pa + k0 + 8);
            float2 v11 = *(const float2*)(pa + 8 * STR + k0 + 8);
            split_pair(v00.x, v00.y, ah0[0], al0[0]);
            split_pair(v10.x, v10.y, ah0[1], al0[1]);
            split_pair(v01.x, v01.y, ah0[2], al0[2]);
            split_pair(v11.x, v11.y, ah0[3], al0[3]);
        }
        {
            const float* pb = pa + 16 * STR;
            float2 v00 = *(const float2*)(pb + k0);
            float2 v10 = *(const float2*)(pb + 8 * STR + k0);
            float2 v01 = *(const float2*)(pb + k0 + 8);
            float2 v11 = *(const float2*)(pb + 8 * STR + k0 + 8);
            split_pair(v00.x, v00.y, ah1[0], al1[0]);
            split_pair(v10.x, v10.y, ah1[1], al1[1]);
            split_pair(v01.x, v01.y, ah1[2], al1[2]);
            split_pair(v11.x, v11.y, ah1[3], al1[3]);
        }
        const uint4* bp = Bf + (ks << 9) + (ch4 << 7) + lane;
        #pragma unroll
        for (int nt = 0; nt < 4; nt++) {
            uint4 b = bp[nt << 5];
            mma16816(acc[nt],     ah0, b.x, b.y);
            mma16816(acc[nt],     al0, b.x, b.y);
            mma16816(acc[nt],     ah0, b.z, b.w);
            mma16816(acc[4 + nt], ah1, b.x, b.y);
            mma16816(acc[4 + nt], al1, b.x, b.y);
            mma16816(acc[4 + nt], ah1, b.z, b.w);
        }
    }
}

// A pre-fragmented variant: fr_hi/fr_lo are [rt'(4)][ks(8)][lane(32)] uint4 arrays.
__device__ __forceinline__ void mma_block_frag(const uint4* __restrict__ fr_hi,
                                               const uint4* __restrict__ fr_lo,
                                               const uint4* __restrict__ Bf,
                                               int wid, int lane, float acc[8][4]) {
    int ch4 = wid & 3, rh = wid >> 2;
    #pragma unroll
    for (int i = 0; i < 8; i++)
        #pragma unroll
        for (int j = 0; j < 4; j++) acc[i][j] = 0.f;
    #pragma unroll
    for (int ks = 0; ks < 8; ks++) {
        int i0 = ((rh * 2) * 8 + ks) * 32 + lane;
        int i1 = ((rh * 2 + 1) * 8 + ks) * 32 + lane;
        uint4 h0 = fr_hi[i0], l0 = fr_lo[i0];
        uint4 h1 = fr_hi[i1], l1 = fr_lo[i1];
        const uint4* bp = Bf + (ks << 9) + (ch4 << 7) + lane;
        #pragma unroll
        for (int nt = 0; nt < 4; nt++) {
            uint4 b = bp[nt << 5];
            mma16816(acc[nt],     (const u32*)&h0, b.x, b.y);
            mma16816(acc[nt],     (const u32*)&l0, b.x, b.y);
            mma16816(acc[nt],     (const u32*)&h0, b.z, b.w);
            mma16816(acc[4 + nt], (const u32*)&h1, b.x, b.y);
            mma16816(acc[4 + nt], (const u32*)&l1, b.x, b.y);
            mma16816(acc[4 + nt], (const u32*)&h1, b.z, b.w);
        }
    }
}

// ---------------- attention: single-pass softmax, packed single-shfl, 4 fma chains ----------------
__device__ void attn(const float* __restrict__ tIn, float* __restrict__ tOut,
                     const u8* __restrict__ sedge, const u16* __restrict__ soff,
                     const float* shas, const float* shad, const float* shb,
                     const float* shea, float* shs, float* shd,
                     float* pool, int doRelu, int tid)
{
    int lane = tid & 31, w = tid >> 5;

    for (int r = w; r < NPG; r += 8) {
        float ss = 0.f, dd = 0.f;
        #pragma unroll
        for (int u = 0; u < 4; u++) {
            int c = lane + 32 * u;
            float hv = tIn[r * STR + c];
            ss += hv * shas[c]; dd += hv * shad[c];
        }
        #pragma unroll
        for (int o = 16; o; o >>= 1) {
            ss += __shfl_down_sync(0xffffffffu, ss, o);
            dd += __shfl_down_sync(0xffffffffu, dd, o);
        }
        if (lane == 0) { shs[r] = ss; shd[r] = dd; }
    }
    __syncthreads();

    int c0 = lane << 2;
    float pacc[4] = {0.f, 0.f, 0.f, 0.f};
    for (int dl = w; dl < NPG; dl += 8) {
        int st = soff[dl];
        int en = (dl < NPG - 1) ? soff[dl + 1] : EPG;
        float db = shd[dl];
        ull a0 = 0ull, a1 = 0ull, b0 = 0ull, b1 = 0ull;
        float den = 0.f;
        for (int base = st; base < en; base += 32) {
            int j = base + lane;
            u32 bits = 0u;
            if (j < en) {
                u32 p = sedge[j];
                int sl = p & 63;
                float lg = shs[sl] + db + shea[p >> 6];
                lg = lg > 0.f ? lg : 0.2f * lg;
                float ex = __expf(lg);
                bits = (__float_as_uint(ex) & ~63u) | (u32)sl;
            }
            den += __uint_as_float(bits & ~63u);
            int cn = min(32, en - base);
            int jj = 0;
            for (; jj + 2 <= cn; jj += 2) {
                u32 v0b = __shfl_sync(0xffffffffu, bits, jj);
                u32 v1b = __shfl_sync(0xffffffffu, bits, jj + 1);
                float e0 = __uint_as_float(v0b & ~63u);
                float e1 = __uint_as_float(v1b & ~63u);
                int s0 = (int)(v0b & 63u), s1 = (int)(v1b & 63u);
                ulonglong2 h0 = *(const ulonglong2*)&tIn[s0 * STR + c0];
                ulonglong2 h1 = *(const ulonglong2*)&tIn[s1 * STR + c0];
                ull pe0 = pk2(e0, e0), pe1 = pk2(e1, e1);
                fma2(a0, pe0, h0.x); fma2(a1, pe0, h0.y);
                fma2(b0, pe1, h1.x); fma2(b1, pe1, h1.y);
            }
            if (jj < cn) {
                u32 v = __shfl_sync(0xffffffffu, bits, jj);
                float e = __uint_as_float(v & ~63u);
                int s = (int)(v & 63u);
                ulonglong2 h = *(const ulonglong2*)&tIn[s * STR + c0];
                ull pe = pk2(e, e);
                fma2(a0, pe, h.x); fma2(a1, pe, h.y);
            }
        }
        #pragma unroll
        for (int o = 16; o; o >>= 1) den += __shfl_xor_sync(0xffffffffu, den, o);
        float inv = 1.f / (den + 1e-16f);
        float v0, v1, v2, v3, w0, w1, w2, w3;
        upk2(a0, v0, v1); upk2(a1, v2, v3);
        upk2(b0, w0, w1); upk2(b1, w2, w3);
        v0 += w0; v1 += w1; v2 += w2; v3 += w3;
        v0 = fmaf(v0, inv, shb[c0]);   v1 = fmaf(v1, inv, shb[c0+1]);
        v2 = fmaf(v2, inv, shb[c0+2]); v3 = fmaf(v3, inv, shb[c0+3]);
        if (doRelu) { v0 = fmaxf(v0,0.f); v1 = fmaxf(v1,0.f); v2 = fmaxf(v2,0.f); v3 = fmaxf(v3,0.f); }
        *(float4*)&tOut[dl * STR + c0] = make_float4(v0, v1, v2, v3);
        if (pool) { pacc[0] += v0; pacc[1] += v1; pacc[2] += v2; pacc[3] += v3; }
    }
    if (pool) {
        atomicAdd(&pool[c0],     pacc[0]);
        atomicAdd(&pool[c0 + 1], pacc[1]);
        atomicAdd(&pool[c0 + 2], pacc[2]);
        atomicAdd(&pool[c0 + 3], pacc[3]);
    }
}

// ---------------- prep kernels ----------------
__global__ void prep_main(const float* __restrict__ node_tab,
                          const float* __restrict__ edge_tab,
                          const float* __restrict__ c1_w,
                          const float* __restrict__ c1_we,
                          const float* __restrict__ c1_ae,
                          const float* __restrict__ c2_we,
                          const float* __restrict__ c2_ae) {
    __shared__ float red[HID];
    int bid = blockIdx.x, tid = threadIdx.x;
    if (bid < NCAT) {
        float acc = 0.f;
        #pragma unroll 8
        for (int k = 0; k < EMB; k++) acc += node_tab[bid*EMB + k] * c1_w[k*HID + tid];
        g_P1[bid*HID + tid] = acc;
    } else {
        for (int combo = 0; combo < 2*NET; combo++) {
            int layer = combo >> 2, t = combo & 3;
            const float* We = layer ? c2_we : c1_we;
            const float* ae = layer ? c2_ae : c1_ae;
            float acc = 0.f;
            #pragma unroll 8
            for (int k = 0; k < EMB; k++) acc += edge_tab[t*EMB + k] * We[k*HID + tid];
            red[tid] = acc * ae[tid];
            __syncthreads();
            if (tid < 32) {
                float s = red[tid] + red[tid+32] + red[tid+64] + red[tid+96];
                #pragma unroll
                for (int o = 16; o; o >>= 1) s += __shfl_down_sync(0xffffffffu, s, o);
                if (tid == 0) g_ea[layer][t] = s;
            }
            __syncthreads();
        }
    }
}

__global__ void prep_w(const float* __restrict__ w0, const float* __restrict__ w1,
                       const float* __restrict__ w2, const float* __restrict__ w3) {
    int b = blockIdx.x, tid = threadIdx.x;
    const float* W = (b == 0) ? w0 : (b == 1) ? w1 : (b == 2) ? w2 : w3;
    int CW = (b == 3) ? NOUT : HID;
    for (int i = tid; i < 4096; i += 256) {
        int ks = i >> 9, rest = i & 511;
        int nt = rest >> 5, l = rest & 31;
        int k = ks * 16 + (l & 3) * 2;
        int n = nt * 8 + (l >> 2);
        float w00=0.f, w01=0.f, w10=0.f, w11=0.f;
        if (n < CW) {
            w00 = W[(size_t)k * CW + n];
            w01 = W[(size_t)(k+1) * CW + n];
            w10 = W[(size_t)(k+8) * CW + n];
            w11 = W[(size_t)(k+9) * CW + n];
        }
        u32 bh0, bl0, bh1, bl1;
        split_pair(w00, w01, bh0, bl0);
        split_pair(w10, w11, bh1, bl1);
        g_Bf[b][i] = make_uint4(bh0, bh1, bl0, bl1);
    }
}

__global__ __launch_bounds__(256) void prep_csr(const int* __restrict__ ei,
                                                const int* __restrict__ eat) {
    __shared__ int cnt[NPG], woff[NPG];
    int g = blockIdx.x, tid = threadIdx.x;
    int ebase = g * EPG;
    if (tid < NPG) cnt[tid] = 0;
    __syncthreads();
    for (int e = tid; e < EPG; e += 256)
        atomicAdd(&cnt[ei[NEDGE + ebase + e] & 63], 1);
    __syncthreads();
    if (tid == 0) {
        int run = 0;
        for (int i = 0; i < NPG; i++) {
            woff[i] = run;
            g_soff[g * NPG + i] = (u16)run;
            run += cnt[i];
        }
    }
    __syncthreads();
    for (int e = tid; e < EPG; e += 256) {
        int sl = ei[ebase + e] & 63;
        int dl = ei[NEDGE + ebase + e] & 63;
        int at = eat[ebase + e];
        int pos = atomicAdd(&woff[dl], 1);
        g_sedge[ebase + pos] = (u8)(sl | (at << 6));
    }
}

// ---------------- mega kernel ----------------
struct MS {
    float tA[NPG*STR];     // P1 -> hw -> h2-frags (hi|lo)
    float tB[NPG*STR];     // h1 -> h2 -> t-frags -> q
    u8    sedge[EPG];
    u16   soff[NPG];
    float shs[NPG], shd[NPG];
    float shas[HID], shad[HID], shb[HID];
    float sheb1[HID], shew2[HID];
    float pool[HID];
    float shea[NET];
    int   codes[NPG];
};

__global__ __launch_bounds__(256, 3) void mega(
    const int* __restrict__ x,
    const float* __restrict__ c1_as, const float* __restrict__ c1_ad, const float* __restrict__ c1_b,
    const float* __restrict__ c2_as, const float* __restrict__ c2_ad, const float* __restrict__ c2_b,
    const float* __restrict__ n_b1, const float* __restrict__ n_b2,
    const float* __restrict__ e_b1, const float* __restrict__ e_w2, const float* __restrict__ e_b2,
    const int* __restrict__ non_edges,
    float* __restrict__ out)
{
    extern __shared__ char smraw[];
    MS& S = *(MS*)smraw;
    int g = blockIdx.x, tid = threadIdx.x;
    int lane = tid & 31, wid = tid >> 5;

    // ---- load structure + layer1 params ----
    if (tid < HID) {
        S.shas[tid] = c1_as[tid]; S.shad[tid] = c1_ad[tid]; S.shb[tid] = c1_b[tid];
        S.sheb1[tid] = e_b1[tid]; S.shew2[tid] = e_w2[tid];
        S.pool[tid] = 0.f;
    }
    if (tid < NET) S.shea[tid] = g_ea[0][tid];
    if (tid < NPG) {
        S.codes[tid] = x[g * NPG + tid];
        S.soff[tid] = g_soff[g * NPG + tid];
    }
    for (int i = tid; i < EPG; i += 256) S.sedge[i] = g_sedge[g * EPG + i];
    __syncthreads();
    // P1 lookup -> tA
    for (int i = tid; i < NPG * 32; i += 256) {
        int r = i >> 5, qq = i & 31;
        *(float4*)&S.tA[r * STR + qq * 4] = ((const float4*)(g_P1 + S.codes[r] * HID))[qq];
    }
    __syncthreads();

    // ---- GAT layer 1: tA -> tB (relu) ----
    attn(S.tA, S.tB, S.sedge, S.soff, S.shas, S.shad, S.shb, S.shea,
         S.shs, S.shd, nullptr, 1, tid);
    __syncthreads();

    int ch4 = wid & 3, rh = wid >> 2;
    int rr = lane >> 2, kc = (lane & 3) * 2;
    float acc[8][4];

    // ---- hw = h1(tB) @ c2_w -> tA ; swap in layer2 params ----
    mma_block(S.tB, g_Bf[0], wid, lane, acc);
    __syncthreads();
    #pragma unroll
    for (int rt = 0; rt < 2; rt++)
        #pragma unroll
        for (int nt = 0; nt < 4; nt++) {
            int r0 = rh * 32 + rt * 16 + rr;
            int c = ch4 * 32 + nt * 8 + kc;
            float* a = acc[rt * 4 + nt];
            *(float2*)&S.tA[r0 * STR + c] = make_float2(a[0], a[1]);
            *(float2*)&S.tA[(r0 + 8) * STR + c] = make_float2(a[2], a[3]);
        }
    if (tid < HID) { S.shas[tid] = c2_as[tid]; S.shad[tid] = c2_ad[tid]; S.shb[tid] = c2_b[tid]; }
    if (tid < NET) S.shea[tid] = g_ea[1][tid];
    __syncthreads();

    // ---- GAT layer 2: tA -> tB (h2) + pool ----
    attn(S.tA, S.tB, S.sedge, S.soff, S.shas, S.shad, S.shb, S.shea,
         S.shs, S.shd, S.pool, 0, tid);
    __syncthreads();

    // ---- pool -> global for stop head ----
    if (tid < HID) g_pool[g * HID + tid] = S.pool[tid];

    // ---- convert h2(tB) -> fragments in tA (hw dead) ----
    uint4* h2_hi = (uint4*)S.tA;
    uint4* h2_lo = h2_hi + 1024;
    for (int i = tid; i < 1024; i += 256) {
        int rt = i >> 8, rest = i & 255;
        int ks = rest >> 5, l = rest & 31;
        int r0 = rt * 16 + (l >> 2);
        int k0 = ks * 16 + (l & 3) * 2;
        float2 v00 = *(const float2*)&S.tB[r0 * STR + k0];
        float2 v10 = *(const float2*)&S.tB[(r0 + 8) * STR + k0];
        float2 v01 = *(const float2*)&S.tB[r0 * STR + k0 + 8];
        float2 v11 = *(const float2*)&S.tB[(r0 + 8) * STR + k0 + 8];
        u32 h0, l0, h1, l1, h2v, l2v, h3, l3;
        split_pair(v00.x, v00.y, h0, l0);
        split_pair(v10.x, v10.y, h1, l1);
        split_pair(v01.x, v01.y, h2v, l2v);
        split_pair(v11.x, v11.y, h3, l3);
        h2_hi[i] = make_uint4(h0, h1, h2v, h3);
        h2_lo[i] = make_uint4(l0, l1, l2v, l3);
    }
    __syncthreads();

    // ---- t = relu(h2frag @ n_w1 + n_b1) -> stored DIRECTLY as fragments in tB ----
    uint4* t_hi = (uint4*)S.tB;
    uint4* t_lo = t_hi + 1024;
    mma_block_frag(h2_hi, h2_lo, g_Bf[1], wid, lane, acc);
    __syncthreads();   // h2 f32 reads (conversion) done; tB overwrite safe
    #pragma unroll
    for (int rt = 0; rt < 2; rt++)
        #pragma unroll
        for (int sp = 0; sp < 2; sp++) {
            float* aA = acc[rt * 4 + 2 * sp];       // (r0, k..k+1), (r0+8, k..k+1)
            float* aB = acc[rt * 4 + 2 * sp + 1];   // (r0, k+8..9), (r0+8, ...)
            int c = ch4 * 32 + sp * 16 + kc;
            float b0 = n_b1[c], b1v = n_b1[c + 1], b8 = n_b1[c + 8], b9 = n_b1[c + 9];
            float v00 = fmaxf(aA[0] + b0, 0.f), v01 = fmaxf(aA[1] + b1v, 0.f);
            float v10 = fmaxf(aA[2] + b0, 0.f), v11 = fmaxf(aA[3] + b1v, 0.f);
            float v20 = fmaxf(aB[0] + b8, 0.f), v21 = fmaxf(aB[1] + b9, 0.f);
            float v30 = fmaxf(aB[2] + b8, 0.f), v31 = fmaxf(aB[3] + b9, 0.f);
            u32 h0, l0, h1, l1, h2v, l2v, h3, l3;
            split_pair(v00, v01, h0, l0);
            split_pair(v10, v11, h1, l1);
            split_pair(v20, v21, h2v, l2v);
            split_pair(v30, v31, h3, l3);
            int idx = ((rh * 2 + rt) * 8 + (ch4 * 2 + sp)) * 32 + lane;
            t_hi[idx] = make_uint4(h0, h1, h2v, h3);
            t_lo[idx] = make_uint4(l0, l1, l2v, l3);
        }
    __syncthreads();

    // ---- addnode = t-frag @ n_w2 + n_b2 -> out ----
    mma_block_frag(t_hi, t_lo, g_Bf[3], wid, lane, acc);
    size_t gbase = (size_t)g * OUTW + 1;
    #pragma unroll
    for (int rt = 0; rt < 2; rt++)
        #pragma unroll
        for (int nt = 0; nt < 4; nt++) {
            int r0 = rh * 32 + rt * 16 + rr;
            int c = ch4 * 32 + nt * 8 + kc;
            float* a = acc[rt * 4 + nt];
            size_t b0p = gbase + (size_t)r0 * NOUT;
            size_t b8p = gbase + (size_t)(r0 + 8) * NOUT;
            if (c < NOUT)     { float bb = n_b2[c];   out[b0p + c]   = a[0] + bb; out[b8p + c]   = a[2] + bb; }
            if (c + 1 < NOUT) { float bb = n_b2[c+1]; out[b0p + c+1] = a[1] + bb; out[b8p + c+1] = a[3] + bb; }
        }
    __syncthreads();   // t-frag reads done before q overwrites tB

    // ---- q = h2frag @ e_w1 -> tB as f32 ----
    mma_block_frag(h2_hi, h2_lo, g_Bf[2], wid, lane, acc);
    #pragma unroll
    for (int rt = 0; rt < 2; rt++)
        #pragma unroll
        for (int nt = 0; nt < 4; nt++) {
            int r0 = rh * 32 + rt * 16 + rr;
            int c = ch4 * 32 + nt * 8 + kc;
            float* a = acc[rt * 4 + nt];
            *(float2*)&S.tB[r0 * STR + c] = make_float2(a[0], a[1]);
            *(float2*)&S.tB[(r0 + 8) * STR + c] = make_float2(a[2], a[3]);
        }
    __syncthreads();

    // ---- addedge head (q in tB) ----
    int nebase = g * NEPG;
    float eb2 = e_b2[0];
    for (int ne = wid; ne < NEPG; ne += 8) {
        int u = non_edges[(size_t)(nebase + ne) * 2]     & 63;
        int v = non_edges[(size_t)(nebase + ne) * 2 + 1] & 63;
        float acc2 = 0.f;
        #pragma unroll
        for (int uu = 0; uu < 4; uu++) {
            int c = lane + 32 * uu;
            float tv = S.tB[u * STR + c] + S.tB[v * STR + c] + S.sheb1[c];
            tv = fmaxf(tv, 0.f);
            acc2 += tv * S.shew2[c];
        }
        #pragma unroll
        for (int o = 16; o; o >>= 1) acc2 += __shfl_down_sync(0xffffffffu, acc2, o);
        if (lane == 0) out[(size_t)g * OUTW + 1 + NPG * NOUT + ne] = acc2 + eb2;
    }
}

// ---------------- stop head kernel: 2 graphs per block ----------------
__global__ __launch_bounds__(256) void stop_kernel(
    const float* __restrict__ s_w1, const float* __restrict__ s_b1,
    const float* __restrict__ s_w2, const float* __restrict__ s_b2,
    float* __restrict__ out)
{
    __shared__ float shp[2][HID];
    __shared__ float shz[2][HID];
    int tid = threadIdx.x;
    int half = tid >> 7, ht = tid & 127;
    int g = blockIdx.x * 2 + half;
    shp[half][ht] = g_pool[g * HID + ht];
    __syncthreads();
    float acc = s_b1[ht];
    #pragma unroll 8
    for (int k = 0; k < HID; k++) acc += shp[half][k] * s_w1[k * HID + ht];
    shz[half][ht] = fmaxf(acc, 0.f) * s_w2[ht];
    __syncthreads();
    int lane = tid & 31, w4 = ht >> 5;
    if (w4 == 0) {
        float s_ = shz[half][lane] + shz[half][lane + 32] + shz[half][lane + 64] + shz[half][lane + 96];
        #pragma unroll
        for (int o = 16; o; o >>= 1) s_ += __shfl_down_sync(0xffffffffu, s_, o);
        if (lane == 0) out[(size_t)g * OUTW] = s_ + s_b2[0];
    }
}

// ---------------- launch ----------------
extern "C" void kernel_launch(void* const* d_in, const int* in_sizes, int n_in,
                              void* d_out, int out_size) {
    const float* node_tab = (const float*)d_in[0];
    const float* edge_tab = (const float*)d_in[1];
    const float* c1_w  = (const float*)d_in[2];
    const float* c1_we = (const float*)d_in[3];
    const float* c1_as = (const float*)d_in[4];
    const float* c1_ad = (const float*)d_in[5];
    const float* c1_ae = (const float*)d_in[6];
    const float* c1_b  = (const float*)d_in[7];
    const float* c2_w  = (const float*)d_in[8];
    const float* c2_we = (const float*)d_in[9];
    const float* c2_as = (const float*)d_in[10];
    const float* c2_ad = (const float*)d_in[11];
    const float* c2_ae = (const float*)d_in[12];
    const float* c2_b  = (const float*)d_in[13];
    const float* s_w1  = (const float*)d_in[14];
    const float* s_b1  = (const float*)d_in[15];
    const float* s_w2  = (const float*)d_in[16];
    const float* s_b2  = (const float*)d_in[17];
    const float* n_w1  = (const float*)d_in[18];
    const float* n_b1  = (const float*)d_in[19];
    const float* n_w2  = (const float*)d_in[20];
    const float* n_b2  = (const float*)d_in[21];
    const float* e_w1  = (const float*)d_in[22];
    const float* e_b1  = (const float*)d_in[23];
    const float* e_w2  = (const float*)d_in[24];
    const float* e_b2  = (const float*)d_in[25];
    const int* x          = (const int*)d_in[26];
    const int* edge_index = (const int*)d_in[27];
    const int* edge_attr  = (const int*)d_in[28];
    const int* non_edges  = (const int*)d_in[29];
    float* out = (float*)d_out;

    cudaFuncSetAttribute(mega, cudaFuncAttributeMaxDynamicSharedMemorySize, (int)sizeof(MS));

    prep_main<<<NCAT + 1, HID>>>(node_tab, edge_tab, c1_w, c1_we, c1_ae, c2_we, c2_ae);
    prep_w<<<4, 256>>>(c2_w, n_w1, e_w1, n_w2);
    prep_csr<<<NB, 256>>>(edge_index, edge_attr);
    mega<<<NB, 256, sizeof(MS)>>>(x, c1_as, c1_ad, c1_b, c2_as, c2_ad, c2_b,
                                  n_b1, n_b2, e_b1, e_w2, e_b2, non_edges, out);
    stop_kernel<<<NB/2, 256>>>(s_w1, s_b1, s_w2, s_b2, out);
}